// round 5
// baseline (speedup 1.0000x reference)
#include <cuda_runtime.h>
#include <cuda_fp16.h>

#define BB 32
#define JJ 2048
#define II 16
#define NN 64
#define DD 32
#define SQ_EPS 1e-7f

// packed 2-wide fp32 FMA (sm_103a; only reachable via PTX)
#define FMA_F32X2(d, a, b, c) \
    asm("fma.rn.f32x2 %0, %1, %2, %3;" : "=l"(d) : "l"(a), "l"(b), "l"(c))
#define UNPACK_F32X2(lo, hi, in) \
    asm("mov.b64 {%0, %1}, %2;" : "=f"(lo), "=f"(hi) : "l"(in))

// ---------------- device scratch (no allocations allowed) ----------------
__device__ __half g_uhat[(size_t)BB * JJ * NN * DD];   // [b][j][n][d], 268 MB
__device__ float  g_v[BB * NN * DD];                   // [b][n][d]
__device__ float  g_blog[(size_t)BB * JJ * NN];        // [b][j][n], 16 MB
__device__ float  g_sp[64 * BB * NN * DD];             // partial s slices, 16 MB

// ---------------- K1: u_hat = einsum('bji,njdi') + partial sum_j u_hat ----------------
// grid = 32 n-pairs * 32 j-chunks (64 j each), 256 threads (8 warps).
#define K1_SMEM ((2 * 8 * 32 * 20 + 32 * 128) * 4)   // Ws 40KB + xs 16KB = 57344 B

__global__ __launch_bounds__(256) void k1_uhat(const float* __restrict__ x,
                                               const float* __restrict__ W) {
    extern __shared__ float sm1[];
    float* Ws = sm1;                    // [n2][jl][d] rows of 16, padded stride 20
    float* xs = sm1 + 2 * 8 * 32 * 20;  // [b][jl*16+i]

    int np = blockIdx.x >> 5;        // n-pair
    int jc = blockIdx.x & 31;        // j-chunk (64 j)
    int t  = threadIdx.x;
    int w  = t >> 5;
    int lane = t & 31;               // d
    int bg = w & 3;                  // b-group: b in [8bg, 8bg+8)
    int js = w >> 2;                 // j-slot: jl in [4js, 4js+4)

    float sacc[2][8];
    #pragma unroll
    for (int nn = 0; nn < 2; nn++)
        #pragma unroll
        for (int bb = 0; bb < 8; bb++) sacc[nn][bb] = 0.f;

    for (int sub = 0; sub < 8; sub++) {
        int j0 = jc * 64 + sub * 8;
        __syncthreads();

        // stage W (streaming; read exactly once chip-wide)
        const float4* W4 = (const float4*)W;
        #pragma unroll
        for (int r = 0; r < 8; r++) {
            int idx = r * 256 + t;
            int n_l = idx >> 10, rem = idx & 1023;
            int jl = rem >> 7, d = (rem >> 2) & 31, q = rem & 3;
            float4 v = __ldcs(&W4[(((np * 2 + n_l) * JJ + (j0 + jl)) << 7) + d * 4 + q]);
            *(float4*)&Ws[((n_l * 8 + jl) * 32 + d) * 20 + q * 4] = v;
        }
        // stage x (reused across 32 np-blocks -> default caching)
        #pragma unroll
        for (int r = 0; r < 4; r++) {
            int idx = r * 256 + t;
            int b = idx >> 5, rr = idx & 31;
            *(float4*)&xs[b * 128 + rr * 4] =
                ((const float4*)x)[(b * JJ + j0) * 4 + rr];
        }
        __syncthreads();

        #pragma unroll
        for (int jj = 0; jj < 4; jj++) {
            int jl = js * 4 + jj;
            int jglob = j0 + jl;
            ulonglong2 wr[2][4];
            #pragma unroll
            for (int nn = 0; nn < 2; nn++) {
                const float* row = &Ws[((nn * 8 + jl) * 32 + lane) * 20];
                wr[nn][0] = *(const ulonglong2*)(row);       // i 0..3
                wr[nn][1] = *(const ulonglong2*)(row + 4);   // i 4..7
                wr[nn][2] = *(const ulonglong2*)(row + 8);   // i 8..11
                wr[nn][3] = *(const ulonglong2*)(row + 12);  // i 12..15
            }
            #pragma unroll
            for (int bb = 0; bb < 8; bb++) {
                int b = bg * 8 + bb;
                const float* xrow = &xs[b * 128 + jl * 16];   // broadcast
                ulonglong2 x0 = *(const ulonglong2*)(xrow);
                ulonglong2 x1 = *(const ulonglong2*)(xrow + 4);
                ulonglong2 x2 = *(const ulonglong2*)(xrow + 8);
                ulonglong2 x3 = *(const ulonglong2*)(xrow + 12);
                #pragma unroll
                for (int nn = 0; nn < 2; nn++) {
                    unsigned long long a2 = 0ull;
                    FMA_F32X2(a2, wr[nn][0].x, x0.x, a2);
                    FMA_F32X2(a2, wr[nn][0].y, x0.y, a2);
                    FMA_F32X2(a2, wr[nn][1].x, x1.x, a2);
                    FMA_F32X2(a2, wr[nn][1].y, x1.y, a2);
                    FMA_F32X2(a2, wr[nn][2].x, x2.x, a2);
                    FMA_F32X2(a2, wr[nn][2].y, x2.y, a2);
                    FMA_F32X2(a2, wr[nn][3].x, x3.x, a2);
                    FMA_F32X2(a2, wr[nn][3].y, x3.y, a2);
                    float lo, hi;
                    UNPACK_F32X2(lo, hi, a2);
                    float acc = lo + hi;
                    sacc[nn][bb] += acc;
                    // streaming store (read back only by k3)
                    __stcs((__half*)&g_uhat[((b * JJ + jglob) * NN + (np * 2 + nn)) * DD + lane],
                           __float2half_rn(acc));
                }
            }
        }
    }

    // flush register partials: slice = jc*2 + js  (64 slices)
    int slice = jc * 2 + js;
    #pragma unroll
    for (int nn = 0; nn < 2; nn++)
        #pragma unroll
        for (int bb = 0; bb < 8; bb++)
            g_sp[(size_t)slice * (BB * NN * DD) +
                 ((bg * 8 + bb) * NN + np * 2 + nn) * DD + lane] = sacc[nn][bb];
}

// ---------------- K2: reduce partial slices, squash, write v ----------------
__global__ __launch_bounds__(256) void k2_squash(int nslices, float prescale,
                                                 float* __restrict__ outp) {
    int g = blockIdx.x * 8 + (threadIdx.x >> 5);   // 0..2047 = b*64+n
    int l = threadIdx.x & 31;                      // lane = d
    float s = 0.f;
    for (int sl = 0; sl < nslices; sl++)
        s += g_sp[(size_t)sl * (BB * NN * DD) + (size_t)g * DD + l];
    s *= prescale;
    float sq = s * s;
    #pragma unroll
    for (int o = 16; o > 0; o >>= 1) sq += __shfl_xor_sync(0xffffffffu, sq, o);
    float scale = sq / ((1.f + sq) * sqrtf(sq + SQ_EPS));
    float* o = outp ? outp : g_v;
    o[(size_t)g * DD + l] = s * scale;
}

// ---------------- K3: fused routing pass (register-resident, prefetched) ----------------
__global__ __launch_bounds__(1024, 1) void k3_route(int first, int last) {
    __shared__ float lg_s[2][16 * 64];   // logits [buf][j][n]
    __shared__ float c_s[2][16 * 64];    // coupling [buf][j][n]

    int b  = blockIdx.x >> 4;
    int jg = blockIdx.x & 15;
    int t  = threadIdx.x;
    int n  = t >> 4;
    int w  = t >> 5;
    int l  = t & 31;

    float2 vv = ((const float2*)g_v)[b * 1024 + t];
    float2 sacc = make_float2(0.f, 0.f);

    const unsigned* ubase =
        (const unsigned*)(g_uhat + ((size_t)b * JJ + jg * 128) * (NN * DD));

    unsigned urA[16], urB[16];

    // prologue: sub 0
    #pragma unroll
    for (int jj = 0; jj < 16; jj++)
        urA[jj] = __ldcs(&ubase[jj * 1024 + t]);

    #pragma unroll
    for (int s = 0; s < 8; s += 2) {
        // prefetch sub s+1 (always valid: s+1 <= 7)
        {
            const unsigned* ug = ubase + (s + 1) * 16 * 1024;
            #pragma unroll
            for (int jj = 0; jj < 16; jj++)
                urB[jj] = __ldcs(&ug[jj * 1024 + t]);
        }

        // ---- process sub s from urA ----
        {
            int buf = 0;
            int j0 = jg * 128 + s * 16;
            #pragma unroll
            for (int jj = 0; jj < 16; jj++) {
                float2 uf = __half22float2(*(const __half2*)&urA[jj]);
                float p = fmaf(uf.x, vv.x, uf.y * vv.y);
                #pragma unroll
                for (int o = 8; o > 0; o >>= 1)
                    p += __shfl_xor_sync(0xffffffffu, p, o);
                if ((t & 15) == 0) lg_s[buf][jj * 64 + n] = p;
            }
            __syncthreads();
            if (w < 16) {
                float* bl = &g_blog[((size_t)b * JJ + (j0 + w)) * NN];
                float p0 = lg_s[buf][w * 64 + l];
                float p1 = lg_s[buf][w * 64 + 32 + l];
                if (!first) { p0 += bl[l]; p1 += bl[l + 32]; }
                if (!last)  { bl[l] = p0; bl[l + 32] = p1; }
                float m = fmaxf(p0, p1);
                #pragma unroll
                for (int o = 16; o > 0; o >>= 1)
                    m = fmaxf(m, __shfl_xor_sync(0xffffffffu, m, o));
                float e0 = __expf(p0 - m), e1 = __expf(p1 - m);
                float ssum = e0 + e1;
                #pragma unroll
                for (int o = 16; o > 0; o >>= 1)
                    ssum += __shfl_xor_sync(0xffffffffu, ssum, o);
                float inv = 1.0f / ssum;
                c_s[buf][w * 64 + l]      = e0 * inv;
                c_s[buf][w * 64 + 32 + l] = e1 * inv;
            }
            __syncthreads();
            #pragma unroll
            for (int jj = 0; jj < 16; jj++) {
                float c = c_s[buf][jj * 64 + n];
                float2 uf = __half22float2(*(const __half2*)&urA[jj]);
                sacc.x = fmaf(c, uf.x, sacc.x);
                sacc.y = fmaf(c, uf.y, sacc.y);
            }
        }

        // prefetch sub s+2 into urA
        if (s + 2 < 8) {
            const unsigned* ug = ubase + (s + 2) * 16 * 1024;
            #pragma unroll
            for (int jj = 0; jj < 16; jj++)
                urA[jj] = __ldcs(&ug[jj * 1024 + t]);
        }

        // ---- process sub s+1 from urB ----
        {
            int buf = 1;
            int j0 = jg * 128 + (s + 1) * 16;
            #pragma unroll
            for (int jj = 0; jj < 16; jj++) {
                float2 uf = __half22float2(*(const __half2*)&urB[jj]);
                float p = fmaf(uf.x, vv.x, uf.y * vv.y);
                #pragma unroll
                for (int o = 8; o > 0; o >>= 1)
                    p += __shfl_xor_sync(0xffffffffu, p, o);
                if ((t & 15) == 0) lg_s[buf][jj * 64 + n] = p;
            }
            __syncthreads();
            if (w < 16) {
                float* bl = &g_blog[((size_t)b * JJ + (j0 + w)) * NN];
                float p0 = lg_s[buf][w * 64 + l];
                float p1 = lg_s[buf][w * 64 + 32 + l];
                if (!first) { p0 += bl[l]; p1 += bl[l + 32]; }
                if (!last)  { bl[l] = p0; bl[l + 32] = p1; }
                float m = fmaxf(p0, p1);
                #pragma unroll
                for (int o = 16; o > 0; o >>= 1)
                    m = fmaxf(m, __shfl_xor_sync(0xffffffffu, m, o));
                float e0 = __expf(p0 - m), e1 = __expf(p1 - m);
                float ssum = e0 + e1;
                #pragma unroll
                for (int o = 16; o > 0; o >>= 1)
                    ssum += __shfl_xor_sync(0xffffffffu, ssum, o);
                float inv = 1.0f / ssum;
                c_s[buf][w * 64 + l]      = e0 * inv;
                c_s[buf][w * 64 + 32 + l] = e1 * inv;
            }
            __syncthreads();
            #pragma unroll
            for (int jj = 0; jj < 16; jj++) {
                float c = c_s[buf][jj * 64 + n];
                float2 uf = __half22float2(*(const __half2*)&urB[jj]);
                sacc.x = fmaf(c, uf.x, sacc.x);
                sacc.y = fmaf(c, uf.y, sacc.y);
            }
        }
    }

    ((float2*)g_sp)[(size_t)jg * (BB * NN * DD / 2) + (size_t)b * 1024 + t] = sacc;
}

// ---------------- launch ----------------
extern "C" void kernel_launch(void* const* d_in, const int* in_sizes, int n_in,
                              void* d_out, int out_size) {
    const float* x = (const float*)d_in[0];
    const float* W = (const float*)d_in[1];
    if (n_in >= 2 && in_sizes[0] != BB * JJ * II) {
        x = (const float*)d_in[1];
        W = (const float*)d_in[0];
    }
    float* out = (float*)d_out;

    cudaFuncSetAttribute(k1_uhat, cudaFuncAttributeMaxDynamicSharedMemorySize, K1_SMEM);

    k1_uhat<<<1024, 256, K1_SMEM>>>(x, W);             // u_hat (fp16) + 64 s-partial slices
    k2_squash<<<256, 256>>>(64, 1.0f / NN, nullptr);   // v0 = squash(sum/64)
    k3_route<<<512, 1024>>>(1, 0);                     // b1, c1, s1 partials (b_old = 0)
    k2_squash<<<256, 256>>>(16, 1.0f, nullptr);        // v1
    k3_route<<<512, 1024>>>(0, 1);                     // b2, c2, s2 partials
    k2_squash<<<256, 256>>>(16, 1.0f, out);            // v2 -> output
}

// round 8
// speedup vs baseline: 1.6604x; 1.6604x over previous
#include <cuda_runtime.h>
#include <cuda_fp16.h>

#define BB 32
#define JJ 2048
#define II 16
#define NN 64
#define DD 32
#define SQ_EPS 1e-7f

// packed 2-wide fp32 FMA (sm_103a; only reachable via PTX)
#define FMA_F32X2(d, a, b, c) \
    asm("fma.rn.f32x2 %0, %1, %2, %3;" : "=l"(d) : "l"(a), "l"(b), "l"(c))
#define UNPACK_F32X2(lo, hi, in) \
    asm("mov.b64 {%0, %1}, %2;" : "=f"(lo), "=f"(hi) : "l"(in))

// ---------------- device scratch (no allocations allowed) ----------------
__device__ __half g_uhat[(size_t)BB * JJ * NN * DD];   // [b][j][n][d], 268 MB
__device__ float  g_v[BB * NN * DD];                   // [b][n][d]
__device__ float  g_blog[(size_t)BB * JJ * NN];        // [b][j][n], 16 MB
__device__ float  g_sp[64 * BB * NN * DD];             // partial s slices, 16 MB

__global__ void k_nop() {}

// ---------------- K1: u_hat = einsum('bji,njdi') + partial sum_j u_hat ----------------
// grid = 32 n-pairs * 32 j-chunks (64 j each), 256 threads (8 warps).  (R4-exact)
#define K1_SMEM ((2 * 8 * 32 * 20 + 32 * 128) * 4)   // Ws 40KB + xs 16KB = 57344 B

__global__ __launch_bounds__(256) void k1_uhat(const float* __restrict__ x,
                                               const float* __restrict__ W) {
    extern __shared__ float sm1[];
    float* Ws = sm1;                    // [n2][jl][d] rows of 16, padded stride 20
    float* xs = sm1 + 2 * 8 * 32 * 20;  // [b][jl*16+i]

    int np = blockIdx.x >> 5;        // n-pair
    int jc = blockIdx.x & 31;        // j-chunk (64 j)
    int t  = threadIdx.x;
    int w  = t >> 5;
    int lane = t & 31;               // d
    int bg = w & 3;                  // b-group: b in [8bg, 8bg+8)
    int js = w >> 2;                 // j-slot: jl in [4js, 4js+4)

    float sacc[2][8];
    #pragma unroll
    for (int nn = 0; nn < 2; nn++)
        #pragma unroll
        for (int bb = 0; bb < 8; bb++) sacc[nn][bb] = 0.f;

    for (int sub = 0; sub < 8; sub++) {
        int j0 = jc * 64 + sub * 8;
        __syncthreads();

        const float4* W4 = (const float4*)W;
        #pragma unroll
        for (int r = 0; r < 8; r++) {
            int idx = r * 256 + t;
            int n_l = idx >> 10, rem = idx & 1023;
            int jl = rem >> 7, d = (rem >> 2) & 31, q = rem & 3;
            float4 v = W4[(((np * 2 + n_l) * JJ + (j0 + jl)) << 7) + d * 4 + q];
            *(float4*)&Ws[((n_l * 8 + jl) * 32 + d) * 20 + q * 4] = v;
        }
        #pragma unroll
        for (int r = 0; r < 4; r++) {
            int idx = r * 256 + t;
            int b = idx >> 5, rr = idx & 31;
            *(float4*)&xs[b * 128 + rr * 4] =
                ((const float4*)x)[(b * JJ + j0) * 4 + rr];
        }
        __syncthreads();

        #pragma unroll
        for (int jj = 0; jj < 4; jj++) {
            int jl = js * 4 + jj;
            int jglob = j0 + jl;
            ulonglong2 wr[2][4];
            #pragma unroll
            for (int nn = 0; nn < 2; nn++) {
                const float* row = &Ws[((nn * 8 + jl) * 32 + lane) * 20];
                wr[nn][0] = *(const ulonglong2*)(row);       // i 0..3
                wr[nn][1] = *(const ulonglong2*)(row + 4);   // i 4..7
                wr[nn][2] = *(const ulonglong2*)(row + 8);   // i 8..11
                wr[nn][3] = *(const ulonglong2*)(row + 12);  // i 12..15
            }
            #pragma unroll
            for (int bb = 0; bb < 8; bb++) {
                int b = bg * 8 + bb;
                const float* xrow = &xs[b * 128 + jl * 16];   // broadcast
                ulonglong2 x0 = *(const ulonglong2*)(xrow);
                ulonglong2 x1 = *(const ulonglong2*)(xrow + 4);
                ulonglong2 x2 = *(const ulonglong2*)(xrow + 8);
                ulonglong2 x3 = *(const ulonglong2*)(xrow + 12);
                #pragma unroll
                for (int nn = 0; nn < 2; nn++) {
                    unsigned long long a2 = 0ull;
                    FMA_F32X2(a2, wr[nn][0].x, x0.x, a2);
                    FMA_F32X2(a2, wr[nn][0].y, x0.y, a2);
                    FMA_F32X2(a2, wr[nn][1].x, x1.x, a2);
                    FMA_F32X2(a2, wr[nn][1].y, x1.y, a2);
                    FMA_F32X2(a2, wr[nn][2].x, x2.x, a2);
                    FMA_F32X2(a2, wr[nn][2].y, x2.y, a2);
                    FMA_F32X2(a2, wr[nn][3].x, x3.x, a2);
                    FMA_F32X2(a2, wr[nn][3].y, x3.y, a2);
                    float lo, hi;
                    UNPACK_F32X2(lo, hi, a2);
                    float acc = lo + hi;
                    sacc[nn][bb] += acc;
                    g_uhat[((b * JJ + jglob) * NN + (np * 2 + nn)) * DD + lane] =
                        __float2half_rn(acc);
                }
            }
        }
    }

    int slice = jc * 2 + js;
    #pragma unroll
    for (int nn = 0; nn < 2; nn++)
        #pragma unroll
        for (int bb = 0; bb < 8; bb++)
            g_sp[(size_t)slice * (BB * NN * DD) +
                 ((bg * 8 + bb) * NN + np * 2 + nn) * DD + lane] = sacc[nn][bb];
}

// ---------------- K2: reduce partial slices, squash, write v ----------------
__global__ __launch_bounds__(256) void k2_squash(int nslices, float prescale,
                                                 float* __restrict__ outp) {
    int g = blockIdx.x * 8 + (threadIdx.x >> 5);   // 0..2047 = b*64+n
    int l = threadIdx.x & 31;                      // lane = d
    float s = 0.f;
    for (int sl = 0; sl < nslices; sl++)
        s += g_sp[(size_t)sl * (BB * NN * DD) + (size_t)g * DD + l];
    s *= prescale;
    float sq = s * s;
    #pragma unroll
    for (int o = 16; o > 0; o >>= 1) sq += __shfl_xor_sync(0xffffffffu, sq, o);
    float scale = sq / ((1.f + sq) * sqrtf(sq + SQ_EPS));
    float* o = outp ? outp : g_v;
    o[(size_t)g * DD + l] = s * scale;
}

// ---------------- K3: fused routing pass, 512 thr / 2 CTAs per SM ----------------
// grid = 32 b * 32 j-groups (64 j each), 512 threads (16 warps).
// thread t owns (n0 = t>>4, dpair = t&15) AND (n0+32, same dpair).
__global__ __launch_bounds__(512, 2) void k3_route(int first, int last) {
    __shared__ float lg_s[8 * 64];   // logits [j][n]
    __shared__ float c_s[8 * 64];    // coupling [j][n]

    int b  = blockIdx.x >> 5;
    int jg = blockIdx.x & 31;
    int t  = threadIdx.x;
    int n0 = t >> 4;      // [0,32)
    int w  = t >> 5;      // warp 0..15
    int l  = t & 31;

    // v[b]: half2-index for (n,dpair) is n*16+dpair; t covers n 0..31, t+512 covers n 32..63
    float2 vv0 = ((const float2*)g_v)[b * 1024 + t];
    float2 vv1 = ((const float2*)g_v)[b * 1024 + 512 + t];
    float2 sacc0 = make_float2(0.f, 0.f);
    float2 sacc1 = make_float2(0.f, 0.f);

    for (int sub = 0; sub < 8; sub++) {
        int j0 = jg * 64 + sub * 8;
        const unsigned* ug = (const unsigned*)(g_uhat + ((size_t)b * JJ + j0) * (NN * DD));

        // 8 j rows, 2 half2 per thread per row — fully coalesced
        unsigned ur0[8], ur1[8];
        #pragma unroll
        for (int jj = 0; jj < 8; jj++) {
            ur0[jj] = ug[jj * 1024 + t];
            ur1[jj] = ug[jj * 1024 + 512 + t];
        }

        // logits: p[j][n] = sum_d v[n][d]*u[j][n][d]; reduce over the 16-lane dpair group
        #pragma unroll
        for (int jj = 0; jj < 8; jj++) {
            float2 uf0 = __half22float2(*(const __half2*)&ur0[jj]);
            float2 uf1 = __half22float2(*(const __half2*)&ur1[jj]);
            float p0 = fmaf(uf0.x, vv0.x, uf0.y * vv0.y);
            float p1 = fmaf(uf1.x, vv1.x, uf1.y * vv1.y);
            #pragma unroll
            for (int o = 8; o > 0; o >>= 1) {
                p0 += __shfl_xor_sync(0xffffffffu, p0, o);
                p1 += __shfl_xor_sync(0xffffffffu, p1, o);
            }
            if ((t & 15) == 0) {
                lg_s[jj * 64 + n0]      = p0;
                lg_s[jj * 64 + n0 + 32] = p1;
            }
        }
        __syncthreads();

        // softmax over n: warp w (w<8) handles j = j0 + w, 2 n per lane
        if (w < 8) {
            float* bl = &g_blog[((size_t)b * JJ + (j0 + w)) * NN];
            float p0 = lg_s[w * 64 + l];
            float p1 = lg_s[w * 64 + 32 + l];
            if (!first) { p0 += bl[l]; p1 += bl[l + 32]; }
            if (!last)  { bl[l] = p0; bl[l + 32] = p1; }
            float m = fmaxf(p0, p1);
            #pragma unroll
            for (int o = 16; o > 0; o >>= 1)
                m = fmaxf(m, __shfl_xor_sync(0xffffffffu, m, o));
            float e0 = __expf(p0 - m), e1 = __expf(p1 - m);
            float ssum = e0 + e1;
            #pragma unroll
            for (int o = 16; o > 0; o >>= 1)
                ssum += __shfl_xor_sync(0xffffffffu, ssum, o);
            float inv = 1.0f / ssum;
            c_s[w * 64 + l]      = e0 * inv;
            c_s[w * 64 + 32 + l] = e1 * inv;
        }
        __syncthreads();

        // s[n][d] += c[j][n] * u[j][n][d] — u still in registers
        #pragma unroll
        for (int jj = 0; jj < 8; jj++) {
            float c0 = c_s[jj * 64 + n0];
            float c1 = c_s[jj * 64 + n0 + 32];
            float2 uf0 = __half22float2(*(const __half2*)&ur0[jj]);
            float2 uf1 = __half22float2(*(const __half2*)&ur1[jj]);
            sacc0.x = fmaf(c0, uf0.x, sacc0.x);
            sacc0.y = fmaf(c0, uf0.y, sacc0.y);
            sacc1.x = fmaf(c1, uf1.x, sacc1.x);
            sacc1.y = fmaf(c1, uf1.y, sacc1.y);
        }
        // no extra barrier needed: c_s rewrites happen only after the next
        // __syncthreads (post-logits), which orders them after these reads
    }

    // non-atomic partials: slice = jg (32 slices), unique (b,n,dpair) per thread
    float2* sp = (float2*)g_sp;
    sp[(size_t)jg * (BB * NN * DD / 2) + (size_t)b * 1024 + t]       = sacc0;
    sp[(size_t)jg * (BB * NN * DD / 2) + (size_t)b * 1024 + 512 + t] = sacc1;
}

// ---------------- launch ----------------
extern "C" void kernel_launch(void* const* d_in, const int* in_sizes, int n_in,
                              void* d_out, int out_size) {
    const float* x = (const float*)d_in[0];
    const float* W = (const float*)d_in[1];
    if (n_in >= 2 && in_sizes[0] != BB * JJ * II) {
        x = (const float*)d_in[1];
        W = (const float*)d_in[0];
    }
    float* out = (float*)d_out;

    cudaFuncSetAttribute(k1_uhat, cudaFuncAttributeMaxDynamicSharedMemorySize, K1_SMEM);

    k1_uhat<<<1024, 256, K1_SMEM>>>(x, W);             // 1: u_hat + 64 s-partial slices
    k2_squash<<<256, 256>>>(64, 1.0f / NN, nullptr);   // 2: v0
    k3_route<<<1024, 512>>>(1, 0);                     // 3: b1, c1, s1 partials
    k2_squash<<<256, 256>>>(32, 1.0f, nullptr);        // 4: v1
    k_nop<<<1, 32>>>();                                // 5: pad so ncu (#6) captures k3
    k3_route<<<1024, 512>>>(0, 1);                     // 6: b2, c2, s2 partials  <- profiled
    k2_squash<<<256, 256>>>(32, 1.0f, out);            // 7: v2 -> output
}

// round 9
// speedup vs baseline: 1.7064x; 1.0277x over previous
#include <cuda_runtime.h>
#include <cuda_fp16.h>

#define BB 32
#define JJ 2048
#define II 16
#define NN 64
#define DD 32
#define SQ_EPS 1e-7f

// packed 2-wide fp32 FMA (sm_103a; only reachable via PTX)
#define FMA_F32X2(d, a, b, c) \
    asm("fma.rn.f32x2 %0, %1, %2, %3;" : "=l"(d) : "l"(a), "l"(b), "l"(c))
#define UNPACK_F32X2(lo, hi, in) \
    asm("mov.b64 {%0, %1}, %2;" : "=f"(lo), "=f"(hi) : "l"(in))

#define CP_ASYNC16(dst_u32, src_ptr) \
    asm volatile("cp.async.cg.shared.global [%0], [%1], 16;\n" \
                 :: "r"(dst_u32), "l"(src_ptr))

// ---------------- device scratch (no allocations allowed) ----------------
__device__ __half g_uhat[(size_t)BB * JJ * NN * DD];   // [b][j][n][d], 268 MB
__device__ float  g_v[BB * NN * DD];                   // [b][n][d]
__device__ float  g_blog[(size_t)BB * JJ * NN];        // [b][j][n], 16 MB
__device__ float  g_sp[64 * BB * NN * DD];             // partial s slices, 16 MB

// ---------------- K1: u_hat = einsum('bji,njdi') + partial sum_j u_hat ----------------
// grid = 32 n-pairs * 32 j-chunks (64 j each), 256 threads (8 warps).
// Double-buffered cp.async staging: stage sub+1 while computing sub.
#define K1_BUF_FLOATS (2 * 8 * 32 * 20 + 32 * 128)    // 14336 floats = 57344 B
#define K1_SMEM (2 * K1_BUF_FLOATS * 4)               // 114688 B

__global__ __launch_bounds__(256) void k1_uhat(const float* __restrict__ x,
                                               const float* __restrict__ W) {
    extern __shared__ float sm1[];

    int np = blockIdx.x >> 5;        // n-pair
    int jc = blockIdx.x & 31;        // j-chunk (64 j)
    int t  = threadIdx.x;
    int w  = t >> 5;
    int lane = t & 31;               // d
    int bg = w & 3;                  // b-group: b in [8bg, 8bg+8)
    int js = w >> 2;                 // j-slot: jl in [4js, 4js+4)

    unsigned sbase = (unsigned)__cvta_generic_to_shared(sm1);
    const float4* W4 = (const float4*)W;
    const float4* X4 = (const float4*)x;

    float sacc[2][8];
    #pragma unroll
    for (int nn = 0; nn < 2; nn++)
        #pragma unroll
        for (int bb = 0; bb < 8; bb++) sacc[nn][bb] = 0.f;

    // ---- async stage of one sub into buffer `buf` ----
    auto stage = [&](int sub, int buf) {
        int j0 = jc * 64 + sub * 8;
        unsigned wb = sbase + buf * (K1_BUF_FLOATS * 4);
        unsigned xb = wb + (2 * 8 * 32 * 20) * 4;
        #pragma unroll
        for (int r = 0; r < 8; r++) {
            int idx = r * 256 + t;
            int n_l = idx >> 10, rem = idx & 1023;
            int jl = rem >> 7, d = (rem >> 2) & 31, q = rem & 3;
            const float4* src = &W4[(((np * 2 + n_l) * JJ + (j0 + jl)) << 7) + d * 4 + q];
            unsigned dst = wb + (((n_l * 8 + jl) * 32 + d) * 20 + q * 4) * 4;
            CP_ASYNC16(dst, src);
        }
        #pragma unroll
        for (int r = 0; r < 4; r++) {
            int idx = r * 256 + t;
            int b = idx >> 5, rr = idx & 31;
            const float4* src = &X4[(b * JJ + j0) * 4 + rr];
            unsigned dst = xb + (b * 128 + rr * 4) * 4;
            CP_ASYNC16(dst, src);
        }
        asm volatile("cp.async.commit_group;\n" ::: "memory");
    };

    stage(0, 0);
    int buf = 0;

    for (int sub = 0; sub < 8; sub++) {
        if (sub + 1 < 8) {
            stage(sub + 1, buf ^ 1);
            asm volatile("cp.async.wait_group 1;\n" ::: "memory");
        } else {
            asm volatile("cp.async.wait_group 0;\n" ::: "memory");
        }
        __syncthreads();   // buffer `buf` (sub's tile) visible to all

        const float* Ws = sm1 + buf * K1_BUF_FLOATS;
        const float* xs = Ws + 2 * 8 * 32 * 20;
        int j0 = jc * 64 + sub * 8;

        #pragma unroll
        for (int jj = 0; jj < 4; jj++) {
            int jl = js * 4 + jj;
            int jglob = j0 + jl;
            ulonglong2 wr[2][4];
            #pragma unroll
            for (int nn = 0; nn < 2; nn++) {
                const float* row = &Ws[((nn * 8 + jl) * 32 + lane) * 20];
                wr[nn][0] = *(const ulonglong2*)(row);       // i 0..3
                wr[nn][1] = *(const ulonglong2*)(row + 4);   // i 4..7
                wr[nn][2] = *(const ulonglong2*)(row + 8);   // i 8..11
                wr[nn][3] = *(const ulonglong2*)(row + 12);  // i 12..15
            }
            #pragma unroll
            for (int bb = 0; bb < 8; bb++) {
                int b = bg * 8 + bb;
                const float* xrow = &xs[b * 128 + jl * 16];   // broadcast
                ulonglong2 x0 = *(const ulonglong2*)(xrow);
                ulonglong2 x1 = *(const ulonglong2*)(xrow + 4);
                ulonglong2 x2 = *(const ulonglong2*)(xrow + 8);
                ulonglong2 x3 = *(const ulonglong2*)(xrow + 12);
                #pragma unroll
                for (int nn = 0; nn < 2; nn++) {
                    unsigned long long a2 = 0ull;
                    FMA_F32X2(a2, wr[nn][0].x, x0.x, a2);
                    FMA_F32X2(a2, wr[nn][0].y, x0.y, a2);
                    FMA_F32X2(a2, wr[nn][1].x, x1.x, a2);
                    FMA_F32X2(a2, wr[nn][1].y, x1.y, a2);
                    FMA_F32X2(a2, wr[nn][2].x, x2.x, a2);
                    FMA_F32X2(a2, wr[nn][2].y, x2.y, a2);
                    FMA_F32X2(a2, wr[nn][3].x, x3.x, a2);
                    FMA_F32X2(a2, wr[nn][3].y, x3.y, a2);
                    float lo, hi;
                    UNPACK_F32X2(lo, hi, a2);
                    float acc = lo + hi;
                    sacc[nn][bb] += acc;
                    g_uhat[((b * JJ + jglob) * NN + (np * 2 + nn)) * DD + lane] =
                        __float2half_rn(acc);
                }
            }
        }
        __syncthreads();   // everyone done reading `buf` before it's restaged
        buf ^= 1;
    }

    int slice = jc * 2 + js;
    #pragma unroll
    for (int nn = 0; nn < 2; nn++)
        #pragma unroll
        for (int bb = 0; bb < 8; bb++)
            g_sp[(size_t)slice * (BB * NN * DD) +
                 ((bg * 8 + bb) * NN + np * 2 + nn) * DD + lane] = sacc[nn][bb];
}

// ---------------- K2: reduce partial slices, squash, write v ----------------
__global__ __launch_bounds__(256) void k2_squash(int nslices, float prescale,
                                                 float* __restrict__ outp) {
    int g = blockIdx.x * 8 + (threadIdx.x >> 5);   // 0..2047 = b*64+n
    int l = threadIdx.x & 31;                      // lane = d
    float s = 0.f;
    for (int sl = 0; sl < nslices; sl++)
        s += g_sp[(size_t)sl * (BB * NN * DD) + (size_t)g * DD + l];
    s *= prescale;
    float sq = s * s;
    #pragma unroll
    for (int o = 16; o > 0; o >>= 1) sq += __shfl_xor_sync(0xffffffffu, sq, o);
    float scale = sq / ((1.f + sq) * sqrtf(sq + SQ_EPS));
    float* o = outp ? outp : g_v;
    o[(size_t)g * DD + l] = s * scale;
}

// ---------------- K3: fused routing pass, 512 thr / 2 CTAs per SM ----------------
__global__ __launch_bounds__(512, 2) void k3_route(int first, int last) {
    __shared__ float lg_s[8 * 64];   // logits [j][n]
    __shared__ float c_s[8 * 64];    // coupling [j][n]

    int b  = blockIdx.x >> 5;
    int jg = blockIdx.x & 31;
    int t  = threadIdx.x;
    int n0 = t >> 4;      // [0,32)
    int w  = t >> 5;      // warp 0..15
    int l  = t & 31;

    float2 vv0 = ((const float2*)g_v)[b * 1024 + t];
    float2 vv1 = ((const float2*)g_v)[b * 1024 + 512 + t];
    float2 sacc0 = make_float2(0.f, 0.f);
    float2 sacc1 = make_float2(0.f, 0.f);

    for (int sub = 0; sub < 8; sub++) {
        int j0 = jg * 64 + sub * 8;
        const unsigned* ug = (const unsigned*)(g_uhat + ((size_t)b * JJ + j0) * (NN * DD));

        unsigned ur0[8], ur1[8];
        #pragma unroll
        for (int jj = 0; jj < 8; jj++) {
            ur0[jj] = ug[jj * 1024 + t];
            ur1[jj] = ug[jj * 1024 + 512 + t];
        }

        #pragma unroll
        for (int jj = 0; jj < 8; jj++) {
            float2 uf0 = __half22float2(*(const __half2*)&ur0[jj]);
            float2 uf1 = __half22float2(*(const __half2*)&ur1[jj]);
            float p0 = fmaf(uf0.x, vv0.x, uf0.y * vv0.y);
            float p1 = fmaf(uf1.x, vv1.x, uf1.y * vv1.y);
            #pragma unroll
            for (int o = 8; o > 0; o >>= 1) {
                p0 += __shfl_xor_sync(0xffffffffu, p0, o);
                p1 += __shfl_xor_sync(0xffffffffu, p1, o);
            }
            if ((t & 15) == 0) {
                lg_s[jj * 64 + n0]      = p0;
                lg_s[jj * 64 + n0 + 32] = p1;
            }
        }
        __syncthreads();

        if (w < 8) {
            float* bl = &g_blog[((size_t)b * JJ + (j0 + w)) * NN];
            float p0 = lg_s[w * 64 + l];
            float p1 = lg_s[w * 64 + 32 + l];
            if (!first) { p0 += bl[l]; p1 += bl[l + 32]; }
            if (!last)  { bl[l] = p0; bl[l + 32] = p1; }
            float m = fmaxf(p0, p1);
            #pragma unroll
            for (int o = 16; o > 0; o >>= 1)
                m = fmaxf(m, __shfl_xor_sync(0xffffffffu, m, o));
            float e0 = __expf(p0 - m), e1 = __expf(p1 - m);
            float ssum = e0 + e1;
            #pragma unroll
            for (int o = 16; o > 0; o >>= 1)
                ssum += __shfl_xor_sync(0xffffffffu, ssum, o);
            float inv = 1.0f / ssum;
            c_s[w * 64 + l]      = e0 * inv;
            c_s[w * 64 + 32 + l] = e1 * inv;
        }
        __syncthreads();

        #pragma unroll
        for (int jj = 0; jj < 8; jj++) {
            float c0 = c_s[jj * 64 + n0];
            float c1 = c_s[jj * 64 + n0 + 32];
            float2 uf0 = __half22float2(*(const __half2*)&ur0[jj]);
            float2 uf1 = __half22float2(*(const __half2*)&ur1[jj]);
            sacc0.x = fmaf(c0, uf0.x, sacc0.x);
            sacc0.y = fmaf(c0, uf0.y, sacc0.y);
            sacc1.x = fmaf(c1, uf1.x, sacc1.x);
            sacc1.y = fmaf(c1, uf1.y, sacc1.y);
        }
        // c_s/lg_s rewrites for the next sub happen only after its post-logits
        // __syncthreads, which orders them after these reads
    }

    float2* sp = (float2*)g_sp;
    sp[(size_t)jg * (BB * NN * DD / 2) + (size_t)b * 1024 + t]       = sacc0;
    sp[(size_t)jg * (BB * NN * DD / 2) + (size_t)b * 1024 + 512 + t] = sacc1;
}

// ---------------- launch ----------------
extern "C" void kernel_launch(void* const* d_in, const int* in_sizes, int n_in,
                              void* d_out, int out_size) {
    const float* x = (const float*)d_in[0];
    const float* W = (const float*)d_in[1];
    if (n_in >= 2 && in_sizes[0] != BB * JJ * II) {
        x = (const float*)d_in[1];
        W = (const float*)d_in[0];
    }
    float* out = (float*)d_out;

    cudaFuncSetAttribute(k1_uhat, cudaFuncAttributeMaxDynamicSharedMemorySize, K1_SMEM);

    k1_uhat<<<1024, 256, K1_SMEM>>>(x, W);             // u_hat + 64 s-partial slices
    k2_squash<<<256, 256>>>(64, 1.0f / NN, nullptr);   // v0
    k3_route<<<1024, 512>>>(1, 0);                     // b1, c1, s1 partials
    k2_squash<<<256, 256>>>(32, 1.0f, nullptr);        // v1
    k3_route<<<1024, 512>>>(0, 1);                     // b2, c2, s2 partials
    k2_squash<<<256, 256>>>(32, 1.0f, out);            // v2 -> output
}

// round 12
// speedup vs baseline: 1.7359x; 1.0173x over previous
#include <cuda_runtime.h>
#include <cuda_fp16.h>

#define BB 32
#define JJ 2048
#define II 16
#define NN 64
#define DD 32
#define SQ_EPS 1e-7f

// packed 2-wide fp32 FMA (sm_103a; only reachable via PTX)
#define FMA_F32X2(d, a, b, c) \
    asm("fma.rn.f32x2 %0, %1, %2, %3;" : "=l"(d) : "l"(a), "l"(b), "l"(c))
#define UNPACK_F32X2(lo, hi, in) \
    asm("mov.b64 {%0, %1}, %2;" : "=f"(lo), "=f"(hi) : "l"(in))

#define CP_ASYNC16(dst_u32, src_ptr) \
    asm volatile("cp.async.cg.shared.global [%0], [%1], 16;\n" \
                 :: "r"(dst_u32), "l"(src_ptr))

// ---------------- device scratch (no allocations allowed) ----------------
__device__ __half g_uhat[(size_t)BB * JJ * NN * DD];   // [b][j][n][d], 268 MB
__device__ float  g_v[BB * NN * DD];                   // [b][n][d]
__device__ float  g_blog[(size_t)BB * JJ * NN];        // [b][j][n], 16 MB
__device__ float  g_sp[64 * BB * NN * DD];             // partial s slices, 16 MB

// ---------------- K1: u_hat = einsum('bji,njdi') + partial sum_j u_hat ----------------
// grid = 32 n-pairs * 32 j-chunks (64 j each), 256 threads (8 warps).
// Double-buffered cp.async staging with SMALL subs (4 j) so 2 CTAs/SM coexist:
// buffer = 2n*4j*32d*20pad + 32b*64 = 7168 floats = 28672 B; x2 = 57344 B.
#define K1_BUF_FLOATS (2 * 4 * 32 * 20 + 32 * 64)
#define K1_SMEM (2 * K1_BUF_FLOATS * 4)

__global__ __launch_bounds__(256) void k1_uhat(const float* __restrict__ x,
                                               const float* __restrict__ W) {
    extern __shared__ float sm1[];

    int np = blockIdx.x >> 5;        // n-pair
    int jc = blockIdx.x & 31;        // j-chunk (64 j)
    int t  = threadIdx.x;
    int w  = t >> 5;
    int lane = t & 31;               // d
    int bg = w & 3;                  // b-group: b in [8bg, 8bg+8)
    int js = w >> 2;                 // j-slot: jl in {2js, 2js+1}

    unsigned sbase = (unsigned)__cvta_generic_to_shared(sm1);
    const float4* W4 = (const float4*)W;
    const float4* X4 = (const float4*)x;

    float sacc[2][8];
    #pragma unroll
    for (int nn = 0; nn < 2; nn++)
        #pragma unroll
        for (int bb = 0; bb < 8; bb++) sacc[nn][bb] = 0.f;

    // ---- async stage of one 4-j sub into buffer `buf` ----
    auto stage = [&](int sub, int buf) {
        int j0 = jc * 64 + sub * 4;
        unsigned wb = sbase + buf * (K1_BUF_FLOATS * 4);
        unsigned xb = wb + (2 * 4 * 32 * 20) * 4;
        // W: 2n * 4j * 32d * 4q = 1024 float4, 4 per thread
        #pragma unroll
        for (int r = 0; r < 4; r++) {
            int idx = r * 256 + t;
            int n_l = idx >> 9, rem = idx & 511;
            int jl = rem >> 7, d = (rem >> 2) & 31, q = rem & 3;
            const float4* src = &W4[(((np * 2 + n_l) * JJ + (j0 + jl)) << 7) + d * 4 + q];
            unsigned dst = wb + (((n_l * 4 + jl) * 32 + d) * 20 + q * 4) * 4;
            CP_ASYNC16(dst, src);
        }
        // x: 32 b * (4j*16i = 64 floats = 16 float4) = 512 float4, 2 per thread
        #pragma unroll
        for (int r = 0; r < 2; r++) {
            int idx = r * 256 + t;
            int b = idx >> 4, rr = idx & 15;
            const float4* src = &X4[(b * JJ + j0) * 4 + rr];
            unsigned dst = xb + (b * 64 + rr * 4) * 4;
            CP_ASYNC16(dst, src);
        }
        asm volatile("cp.async.commit_group;\n" ::: "memory");
    };

    stage(0, 0);
    int buf = 0;

    for (int sub = 0; sub < 16; sub++) {
        if (sub + 1 < 16) {
            stage(sub + 1, buf ^ 1);
            asm volatile("cp.async.wait_group 1;\n" ::: "memory");
        } else {
            asm volatile("cp.async.wait_group 0;\n" ::: "memory");
        }
        __syncthreads();   // buffer `buf` (sub's tile) visible to all

        const float* Ws = sm1 + buf * K1_BUF_FLOATS;
        const float* xs = Ws + 2 * 4 * 32 * 20;
        int j0 = jc * 64 + sub * 4;

        #pragma unroll
        for (int jj = 0; jj < 2; jj++) {
            int jl = js * 2 + jj;
            int jglob = j0 + jl;
            ulonglong2 wr[2][4];
            #pragma unroll
            for (int nn = 0; nn < 2; nn++) {
                const float* row = &Ws[((nn * 4 + jl) * 32 + lane) * 20];
                wr[nn][0] = *(const ulonglong2*)(row);       // i 0..3
                wr[nn][1] = *(const ulonglong2*)(row + 4);   // i 4..7
                wr[nn][2] = *(const ulonglong2*)(row + 8);   // i 8..11
                wr[nn][3] = *(const ulonglong2*)(row + 12);  // i 12..15
            }
            #pragma unroll
            for (int bb = 0; bb < 8; bb++) {
                int b = bg * 8 + bb;
                const float* xrow = &xs[b * 64 + jl * 16];    // broadcast
                ulonglong2 x0 = *(const ulonglong2*)(xrow);
                ulonglong2 x1 = *(const ulonglong2*)(xrow + 4);
                ulonglong2 x2 = *(const ulonglong2*)(xrow + 8);
                ulonglong2 x3 = *(const ulonglong2*)(xrow + 12);
                #pragma unroll
                for (int nn = 0; nn < 2; nn++) {
                    unsigned long long a2 = 0ull;
                    FMA_F32X2(a2, wr[nn][0].x, x0.x, a2);
                    FMA_F32X2(a2, wr[nn][0].y, x0.y, a2);
                    FMA_F32X2(a2, wr[nn][1].x, x1.x, a2);
                    FMA_F32X2(a2, wr[nn][1].y, x1.y, a2);
                    FMA_F32X2(a2, wr[nn][2].x, x2.x, a2);
                    FMA_F32X2(a2, wr[nn][2].y, x2.y, a2);
                    FMA_F32X2(a2, wr[nn][3].x, x3.x, a2);
                    FMA_F32X2(a2, wr[nn][3].y, x3.y, a2);
                    float lo, hi;
                    UNPACK_F32X2(lo, hi, a2);
                    float acc = lo + hi;
                    sacc[nn][bb] += acc;
                    g_uhat[((b * JJ + jglob) * NN + (np * 2 + nn)) * DD + lane] =
                        __float2half_rn(acc);
                }
            }
        }
        __syncthreads();   // everyone done reading `buf` before it's restaged
        buf ^= 1;
    }

    // flush register partials: slice = jc*2 + js  (64 slices)
    int slice = jc * 2 + js;
    #pragma unroll
    for (int nn = 0; nn < 2; nn++)
        #pragma unroll
        for (int bb = 0; bb < 8; bb++)
            g_sp[(size_t)slice * (BB * NN * DD) +
                 ((bg * 8 + bb) * NN + np * 2 + nn) * DD + lane] = sacc[nn][bb];
}

// ---------------- K2: reduce partial slices, squash, write v ----------------
__global__ __launch_bounds__(256) void k2_squash(int nslices, float prescale,
                                                 float* __restrict__ outp) {
    int g = blockIdx.x * 8 + (threadIdx.x >> 5);   // 0..2047 = b*64+n
    int l = threadIdx.x & 31;                      // lane = d
    float s = 0.f;
    for (int sl = 0; sl < nslices; sl++)
        s += g_sp[(size_t)sl * (BB * NN * DD) + (size_t)g * DD + l];
    s *= prescale;
    float sq = s * s;
    #pragma unroll
    for (int o = 16; o > 0; o >>= 1) sq += __shfl_xor_sync(0xffffffffu, sq, o);
    float scale = sq / ((1.f + sq) * sqrtf(sq + SQ_EPS));
    float* o = outp ? outp : g_v;
    o[(size_t)g * DD + l] = s * scale;
}

// ---------------- K3: fused routing pass, 512 thr / 2 CTAs per SM ----------------
__global__ __launch_bounds__(512, 2) void k3_route(int first, int last) {
    __shared__ float lg_s[8 * 64];
    __shared__ float c_s[8 * 64];

    int b  = blockIdx.x >> 5;
    int jg = blockIdx.x & 31;
    int t  = threadIdx.x;
    int n0 = t >> 4;
    int w  = t >> 5;
    int l  = t & 31;

    float2 vv0 = ((const float2*)g_v)[b * 1024 + t];
    float2 vv1 = ((const float2*)g_v)[b * 1024 + 512 + t];
    float2 sacc0 = make_float2(0.f, 0.f);
    float2 sacc1 = make_float2(0.f, 0.f);

    for (int sub = 0; sub < 8; sub++) {
        int j0 = jg * 64 + sub * 8;
        const unsigned* ug = (const unsigned*)(g_uhat + ((size_t)b * JJ + j0) * (NN * DD));

        unsigned ur0[8], ur1[8];
        #pragma unroll
        for (int jj = 0; jj < 8; jj++) {
            ur0[jj] = ug[jj * 1024 + t];
            ur1[jj] = ug[jj * 1024 + 512 + t];
        }

        #pragma unroll
        for (int jj = 0; jj < 8; jj++) {
            float2 uf0 = __half22float2(*(const __half2*)&ur0[jj]);
            float2 uf1 = __half22float2(*(const __half2*)&ur1[jj]);
            float p0 = fmaf(uf0.x, vv0.x, uf0.y * vv0.y);
            float p1 = fmaf(uf1.x, vv1.x, uf1.y * vv1.y);
            #pragma unroll
            for (int o = 8; o > 0; o >>= 1) {
                p0 += __shfl_xor_sync(0xffffffffu, p0, o);
                p1 += __shfl_xor_sync(0xffffffffu, p1, o);
            }
            if ((t & 15) == 0) {
                lg_s[jj * 64 + n0]      = p0;
                lg_s[jj * 64 + n0 + 32] = p1;
            }
        }
        __syncthreads();

        if (w < 8) {
            float* bl = &g_blog[((size_t)b * JJ + (j0 + w)) * NN];
            float p0 = lg_s[w * 64 + l];
            float p1 = lg_s[w * 64 + 32 + l];
            if (!first) { p0 += bl[l]; p1 += bl[l + 32]; }
            if (!last)  { bl[l] = p0; bl[l + 32] = p1; }
            float m = fmaxf(p0, p1);
            #pragma unroll
            for (int o = 16; o > 0; o >>= 1)
                m = fmaxf(m, __shfl_xor_sync(0xffffffffu, m, o));
            float e0 = __expf(p0 - m), e1 = __expf(p1 - m);
            float ssum = e0 + e1;
            #pragma unroll
            for (int o = 16; o > 0; o >>= 1)
                ssum += __shfl_xor_sync(0xffffffffu, ssum, o);
            float inv = 1.0f / ssum;
            c_s[w * 64 + l]      = e0 * inv;
            c_s[w * 64 + 32 + l] = e1 * inv;
        }
        __syncthreads();

        #pragma unroll
        for (int jj = 0; jj < 8; jj++) {
            float c0 = c_s[jj * 64 + n0];
            float c1 = c_s[jj * 64 + n0 + 32];
            float2 uf0 = __half22float2(*(const __half2*)&ur0[jj]);
            float2 uf1 = __half22float2(*(const __half2*)&ur1[jj]);
            sacc0.x = fmaf(c0, uf0.x, sacc0.x);
            sacc0.y = fmaf(c0, uf0.y, sacc0.y);
            sacc1.x = fmaf(c1, uf1.x, sacc1.x);
            sacc1.y = fmaf(c1, uf1.y, sacc1.y);
        }
    }

    float2* sp = (float2*)g_sp;
    sp[(size_t)jg * (BB * NN * DD / 2) + (size_t)b * 1024 + t]       = sacc0;
    sp[(size_t)jg * (BB * NN * DD / 2) + (size_t)b * 1024 + 512 + t] = sacc1;
}

// ---------------- launch ----------------
extern "C" void kernel_launch(void* const* d_in, const int* in_sizes, int n_in,
                              void* d_out, int out_size) {
    const float* x = (const float*)d_in[0];
    const float* W = (const float*)d_in[1];
    if (n_in >= 2 && in_sizes[0] != BB * JJ * II) {
        x = (const float*)d_in[1];
        W = (const float*)d_in[0];
    }
    float* out = (float*)d_out;

    cudaFuncSetAttribute(k1_uhat, cudaFuncAttributeMaxDynamicSharedMemorySize, K1_SMEM);

    k1_uhat<<<1024, 256, K1_SMEM>>>(x, W);             // u_hat + 64 s-partial slices
    k2_squash<<<256, 256>>>(64, 1.0f / NN, nullptr);   // v0
    k3_route<<<1024, 512>>>(1, 0);                     // b1, c1, s1 partials
    k2_squash<<<256, 256>>>(32, 1.0f, nullptr);        // v1
    k3_route<<<1024, 512>>>(0, 1);                     // b2, c2, s2 partials
    k2_squash<<<256, 256>>>(32, 1.0f, out);            // v2 -> output
}

// round 13
// speedup vs baseline: 1.8469x; 1.0640x over previous
#include <cuda_runtime.h>
#include <cuda_fp16.h>

#define BB 32
#define JJ 2048
#define II 16
#define NN 64
#define DD 32
#define SQ_EPS 1e-7f

// packed 2-wide fp32 FMA (sm_103a; only reachable via PTX)
#define FMA_F32X2(d, a, b, c) \
    asm("fma.rn.f32x2 %0, %1, %2, %3;" : "=l"(d) : "l"(a), "l"(b), "l"(c))
#define UNPACK_F32X2(lo, hi, in) \
    asm("mov.b64 {%0, %1}, %2;" : "=f"(lo), "=f"(hi) : "l"(in))

#define CP_ASYNC16(dst_u32, src_ptr) \
    asm volatile("cp.async.cg.shared.global [%0], [%1], 16;\n" \
                 :: "r"(dst_u32), "l"(src_ptr))

// ---------------- device scratch (no allocations allowed) ----------------
__device__ __half g_uhat[(size_t)BB * JJ * NN * DD];   // [b][j][n][d], 268 MB
__device__ float  g_v[BB * NN * DD];                   // [b][n][d]
__device__ float  g_blog[(size_t)BB * JJ * NN];        // [b][j][n], 16 MB
__device__ float  g_sp[64 * BB * NN * DD];             // partial s slices, 16 MB

// ---------------- K1: u_hat = einsum('bji,njdi') + partial sum_j u_hat ----------------
// grid = 32 n-pairs * 32 j-chunks (64 j each), 256 threads (8 warps).
// Lane owns (n = lane>>4, dpair = lane&15): computes d=2dp,2dp+1 -> one half2 STG.
// W staged dpair-major, 32 floats/row, pad to 36 (conflict-free, 16B aligned).
// Double-buffered cp.async staging (4 j per sub, 16 subs).
#define K1_W_FLOATS (2 * 4 * 16 * 36)                 // 4608
#define K1_BUF_FLOATS (K1_W_FLOATS + 32 * 64)         // + xs 2048 = 6656
#define K1_SMEM (2 * K1_BUF_FLOATS * 4)               // 53248 B

__global__ __launch_bounds__(256) void k1_uhat(const float* __restrict__ x,
                                               const float* __restrict__ W) {
    extern __shared__ float sm1[];

    int np = blockIdx.x >> 5;        // n-pair
    int jc = blockIdx.x & 31;        // j-chunk (64 j)
    int t  = threadIdx.x;
    int w  = t >> 5;
    int lane = t & 31;
    int dp = lane & 15;              // d pair: d = 2dp, 2dp+1
    int nl = lane >> 4;              // n local (0/1)
    int bg = w & 3;                  // b-group: b in [8bg, 8bg+8)
    int js = w >> 2;                 // j-slot: jl in {2js, 2js+1}
    int n  = np * 2 + nl;

    unsigned sbase = (unsigned)__cvta_generic_to_shared(sm1);
    const float4* W4 = (const float4*)W;
    const float4* X4 = (const float4*)x;

    float2 sacc[8];
    #pragma unroll
    for (int bb = 0; bb < 8; bb++) sacc[bb] = make_float2(0.f, 0.f);

    // ---- async stage of one 4-j sub into buffer `buf` ----
    auto stage = [&](int sub, int buf) {
        int j0 = jc * 64 + sub * 4;
        unsigned wb = sbase + buf * (K1_BUF_FLOATS * 4);
        unsigned xb = wb + K1_W_FLOATS * 4;
        // W: 2n * 4j * 32d * 4q = 1024 float4, 4 per thread; dpair-major pad-36
        #pragma unroll
        for (int r = 0; r < 4; r++) {
            int idx = r * 256 + t;
            int n_l = idx >> 9, rem = idx & 511;
            int jl = rem >> 7, d = (rem >> 2) & 31, q = rem & 3;
            const float4* src = &W4[(((np * 2 + n_l) * JJ + (j0 + jl)) << 7) + d * 4 + q];
            unsigned off = ((n_l * 4 + jl) * 16 + (d >> 1)) * 36 + (d & 1) * 16 + q * 4;
            CP_ASYNC16(wb + off * 4, src);
        }
        // x: 32 b * 16 float4 = 512, 2 per thread
        #pragma unroll
        for (int r = 0; r < 2; r++) {
            int idx = r * 256 + t;
            int b = idx >> 4, rr = idx & 15;
            const float4* src = &X4[(b * JJ + j0) * 4 + rr];
            CP_ASYNC16(xb + (b * 64 + rr * 4) * 4, src);
        }
        asm volatile("cp.async.commit_group;\n" ::: "memory");
    };

    stage(0, 0);
    int buf = 0;

    for (int sub = 0; sub < 16; sub++) {
        if (sub + 1 < 16) {
            stage(sub + 1, buf ^ 1);
            asm volatile("cp.async.wait_group 1;\n" ::: "memory");
        } else {
            asm volatile("cp.async.wait_group 0;\n" ::: "memory");
        }
        __syncthreads();   // buffer `buf` (sub's tile) visible to all

        const float* Ws = sm1 + buf * K1_BUF_FLOATS;
        const float* xs = Ws + K1_W_FLOATS;
        int j0 = jc * 64 + sub * 4;

        #pragma unroll
        for (int jj = 0; jj < 2; jj++) {
            int jl = js * 2 + jj;
            int jglob = j0 + jl;
            // this thread's two W rows (d=2dp at [0..15], d=2dp+1 at [16..31])
            const float* row = &Ws[((nl * 4 + jl) * 16 + dp) * 36];
            ulonglong2 wa0 = *(const ulonglong2*)(row);        // d0, i 0..3
            ulonglong2 wa1 = *(const ulonglong2*)(row + 4);    // d0, i 4..7
            ulonglong2 wa2 = *(const ulonglong2*)(row + 8);    // d0, i 8..11
            ulonglong2 wa3 = *(const ulonglong2*)(row + 12);   // d0, i 12..15
            ulonglong2 wb0 = *(const ulonglong2*)(row + 16);   // d1, i 0..3
            ulonglong2 wb1 = *(const ulonglong2*)(row + 20);
            ulonglong2 wb2 = *(const ulonglong2*)(row + 24);
            ulonglong2 wb3 = *(const ulonglong2*)(row + 28);

            __half2* up = (__half2*)g_uhat + ((size_t)jglob * NN + n) * 16 + dp;

            #pragma unroll
            for (int bb = 0; bb < 8; bb++) {
                int b = bg * 8 + bb;
                const float* xrow = &xs[b * 64 + jl * 16];     // broadcast
                ulonglong2 x0 = *(const ulonglong2*)(xrow);
                ulonglong2 x1 = *(const ulonglong2*)(xrow + 4);
                ulonglong2 x2 = *(const ulonglong2*)(xrow + 8);
                ulonglong2 x3 = *(const ulonglong2*)(xrow + 12);

                unsigned long long a0 = 0ull, a1 = 0ull;
                FMA_F32X2(a0, wa0.x, x0.x, a0);  FMA_F32X2(a1, wb0.x, x0.x, a1);
                FMA_F32X2(a0, wa0.y, x0.y, a0);  FMA_F32X2(a1, wb0.y, x0.y, a1);
                FMA_F32X2(a0, wa1.x, x1.x, a0);  FMA_F32X2(a1, wb1.x, x1.x, a1);
                FMA_F32X2(a0, wa1.y, x1.y, a0);  FMA_F32X2(a1, wb1.y, x1.y, a1);
                FMA_F32X2(a0, wa2.x, x2.x, a0);  FMA_F32X2(a1, wb2.x, x2.x, a1);
                FMA_F32X2(a0, wa2.y, x2.y, a0);  FMA_F32X2(a1, wb2.y, x2.y, a1);
                FMA_F32X2(a0, wa3.x, x3.x, a0);  FMA_F32X2(a1, wb3.x, x3.x, a1);
                FMA_F32X2(a0, wa3.y, x3.y, a0);  FMA_F32X2(a1, wb3.y, x3.y, a1);

                float l0, h0, l1, h1;
                UNPACK_F32X2(l0, h0, a0);
                UNPACK_F32X2(l1, h1, a1);
                float e0 = l0 + h0;   // d = 2dp
                float e1 = l1 + h1;   // d = 2dp+1
                sacc[bb].x += e0;
                sacc[bb].y += e1;
                up[(size_t)b * (JJ * NN * 16)] = __floats2half2_rn(e0, e1);
            }
        }
        __syncthreads();   // everyone done reading `buf` before it's restaged
        buf ^= 1;
    }

    // flush register partials: slice = jc*2 + js  (64 slices); float2 per (b,n,dp)
    int slice = jc * 2 + js;
    float2* sp2 = (float2*)g_sp;
    #pragma unroll
    for (int bb = 0; bb < 8; bb++)
        sp2[(size_t)slice * (BB * NN * 16) + ((size_t)(bg * 8 + bb) * NN + n) * 16 + dp]
            = sacc[bb];
}

// ---------------- K2: reduce partial slices (MLP=4), squash, write v ----------------
__global__ __launch_bounds__(256) void k2_squash(int nslices, float prescale,
                                                 float* __restrict__ outp) {
    int g = blockIdx.x * 8 + (threadIdx.x >> 5);   // 0..2047 = b*64+n
    int l = threadIdx.x & 31;                      // lane = d
    float s0 = 0.f, s1 = 0.f, s2 = 0.f, s3 = 0.f;
    for (int sl = 0; sl < nslices; sl += 4) {
        s0 += g_sp[(size_t)(sl + 0) * (BB * NN * DD) + (size_t)g * DD + l];
        s1 += g_sp[(size_t)(sl + 1) * (BB * NN * DD) + (size_t)g * DD + l];
        s2 += g_sp[(size_t)(sl + 2) * (BB * NN * DD) + (size_t)g * DD + l];
        s3 += g_sp[(size_t)(sl + 3) * (BB * NN * DD) + (size_t)g * DD + l];
    }
    float s = ((s0 + s1) + (s2 + s3)) * prescale;
    float sq = s * s;
    #pragma unroll
    for (int o = 16; o > 0; o >>= 1) sq += __shfl_xor_sync(0xffffffffu, sq, o);
    float scale = sq / ((1.f + sq) * sqrtf(sq + SQ_EPS));
    float* o = outp ? outp : g_v;
    o[(size_t)g * DD + l] = s * scale;
}

// ---------------- K3: fused routing pass, 512 thr / 2 CTAs per SM ----------------
__global__ __launch_bounds__(512, 2) void k3_route(int first, int last) {
    __shared__ float lg_s[8 * 64];
    __shared__ float c_s[8 * 64];

    int b  = blockIdx.x >> 5;
    int jg = blockIdx.x & 31;
    int t  = threadIdx.x;
    int n0 = t >> 4;
    int w  = t >> 5;
    int l  = t & 31;

    float2 vv0 = ((const float2*)g_v)[b * 1024 + t];
    float2 vv1 = ((const float2*)g_v)[b * 1024 + 512 + t];
    float2 sacc0 = make_float2(0.f, 0.f);
    float2 sacc1 = make_float2(0.f, 0.f);

    for (int sub = 0; sub < 8; sub++) {
        int j0 = jg * 64 + sub * 8;
        const unsigned* ug = (const unsigned*)(g_uhat + ((size_t)b * JJ + j0) * (NN * DD));

        unsigned ur0[8], ur1[8];
        #pragma unroll
        for (int jj = 0; jj < 8; jj++) {
            ur0[jj] = ug[jj * 1024 + t];
            ur1[jj] = ug[jj * 1024 + 512 + t];
        }

        #pragma unroll
        for (int jj = 0; jj < 8; jj++) {
            float2 uf0 = __half22float2(*(const __half2*)&ur0[jj]);
            float2 uf1 = __half22float2(*(const __half2*)&ur1[jj]);
            float p0 = fmaf(uf0.x, vv0.x, uf0.y * vv0.y);
            float p1 = fmaf(uf1.x, vv1.x, uf1.y * vv1.y);
            #pragma unroll
            for (int o = 8; o > 0; o >>= 1) {
                p0 += __shfl_xor_sync(0xffffffffu, p0, o);
                p1 += __shfl_xor_sync(0xffffffffu, p1, o);
            }
            if ((t & 15) == 0) {
                lg_s[jj * 64 + n0]      = p0;
                lg_s[jj * 64 + n0 + 32] = p1;
            }
        }
        __syncthreads();

        if (w < 8) {
            float* bl = &g_blog[((size_t)b * JJ + (j0 + w)) * NN];
            float p0 = lg_s[w * 64 + l];
            float p1 = lg_s[w * 64 + 32 + l];
            if (!first) { p0 += bl[l]; p1 += bl[l + 32]; }
            if (!last)  { bl[l] = p0; bl[l + 32] = p1; }
            float m = fmaxf(p0, p1);
            #pragma unroll
            for (int o = 16; o > 0; o >>= 1)
                m = fmaxf(m, __shfl_xor_sync(0xffffffffu, m, o));
            float e0 = __expf(p0 - m), e1 = __expf(p1 - m);
            float ssum = e0 + e1;
            #pragma unroll
            for (int o = 16; o > 0; o >>= 1)
                ssum += __shfl_xor_sync(0xffffffffu, ssum, o);
            float inv = 1.0f / ssum;
            c_s[w * 64 + l]      = e0 * inv;
            c_s[w * 64 + 32 + l] = e1 * inv;
        }
        __syncthreads();

        #pragma unroll
        for (int jj = 0; jj < 8; jj++) {
            float c0 = c_s[jj * 64 + n0];
            float c1 = c_s[jj * 64 + n0 + 32];
            float2 uf0 = __half22float2(*(const __half2*)&ur0[jj]);
            float2 uf1 = __half22float2(*(const __half2*)&ur1[jj]);
            sacc0.x = fmaf(c0, uf0.x, sacc0.x);
            sacc0.y = fmaf(c0, uf0.y, sacc0.y);
            sacc1.x = fmaf(c1, uf1.x, sacc1.x);
            sacc1.y = fmaf(c1, uf1.y, sacc1.y);
        }
    }

    float2* sp = (float2*)g_sp;
    sp[(size_t)jg * (BB * NN * DD / 2) + (size_t)b * 1024 + t]       = sacc0;
    sp[(size_t)jg * (BB * NN * DD / 2) + (size_t)b * 1024 + 512 + t] = sacc1;
}

// ---------------- launch ----------------
extern "C" void kernel_launch(void* const* d_in, const int* in_sizes, int n_in,
                              void* d_out, int out_size) {
    const float* x = (const float*)d_in[0];
    const float* W = (const float*)d_in[1];
    if (n_in >= 2 && in_sizes[0] != BB * JJ * II) {
        x = (const float*)d_in[1];
        W = (const float*)d_in[0];
    }
    float* out = (float*)d_out;

    cudaFuncSetAttribute(k1_uhat, cudaFuncAttributeMaxDynamicSharedMemorySize, K1_SMEM);

    k1_uhat<<<1024, 256, K1_SMEM>>>(x, W);             // u_hat + 64 s-partial slices
    k2_squash<<<256, 256>>>(64, 1.0f / NN, nullptr);   // v0
    k3_route<<<1024, 512>>>(1, 0);                     // b1, c1, s1 partials
    k2_squash<<<256, 256>>>(32, 1.0f, nullptr);        // v1
    k3_route<<<1024, 512>>>(0, 1);                     // b2, c2, s2 partials
    k2_squash<<<256, 256>>>(32, 1.0f, out);            // v2 -> output
}